// round 14
// baseline (speedup 1.0000x reference)
#include <cuda_runtime.h>
#include <cuda_fp16.h>
#include <cstdint>
#include <math.h>

#define B_  2
#define T_  1024
#define E_  768
#define H_  12
#define L_  6
#define V_  32000
#define DH_ 64
#define DF_ 3072
#define M_  (B_*T_)

typedef __half fp16;

// ========================= helpers =========================
__device__ __forceinline__ uint32_t smem_u32(const void* p) {
    uint32_t a;
    asm("{ .reg .u64 t; cvta.to.shared.u64 t, %1; cvt.u32.u64 %0, t; }" : "=r"(a) : "l"(p));
    return a;
}
#define LDSM4(r, addr) \
    asm volatile("ldmatrix.sync.aligned.m8n8.x4.shared.b16 {%0,%1,%2,%3}, [%4];" \
        : "=r"((r)[0]), "=r"((r)[1]), "=r"((r)[2]), "=r"((r)[3]) : "r"(addr))
#define MMA_FP16(d, a, b0, b1) \
    asm volatile("mma.sync.aligned.m16n8k16.row.col.f32.f16.f16.f32 " \
        "{%0,%1,%2,%3}, {%4,%5,%6,%7}, {%8,%9}, {%0,%1,%2,%3};" \
        : "+f"((d)[0]), "+f"((d)[1]), "+f"((d)[2]), "+f"((d)[3]) \
        : "r"((a)[0]), "r"((a)[1]), "r"((a)[2]), "r"((a)[3]), "r"(b0), "r"(b1))
#define CP_ASYNC16(dst, src) \
    asm volatile("cp.async.cg.shared.global [%0], [%1], 16;" :: "r"(dst), "l"(src))
#define CP_COMMIT() asm volatile("cp.async.commit_group;" ::: "memory")
#define CP_WAIT1()  asm volatile("cp.async.wait_group 1;" ::: "memory")
#define CP_WAIT0()  asm volatile("cp.async.wait_group 0;" ::: "memory")

__device__ __forceinline__ uint32_t f2h2(float x, float y) {
    __half2 h = __floats2half2_rn(x, y);
    return *(uint32_t*)&h;
}

// ========================= device scratch (single fp16 planes) =========================
__device__ fp16 g_wqkv[L_*3*E_*E_];
__device__ fp16 g_wo[L_*E_*E_];
__device__ fp16 g_w1[L_*DF_*E_];
__device__ fp16 g_w2[L_*E_*DF_];
__device__ fp16 g_wlm[V_*E_];
__device__ fp16 g_h[M_*E_];
__device__ fp16 g_q[M_*E_];
__device__ fp16 g_k[M_*E_];
__device__ fp16 g_v[M_*E_];
__device__ fp16 g_vt[M_*E_];
__device__ fp16 g_o[M_*E_];
__device__ fp16 g_ff[M_*DF_];
__device__ float g_x[M_*E_];
__device__ float g_part[3LL*M_*E_];

// ========================= small kernels =========================
__global__ __launch_bounds__(256)
void conv_kernel(const float4* __restrict__ src, __half2* __restrict__ dst, int n4)
{
    int i = blockIdx.x * 256 + threadIdx.x;
    if (i >= n4) return;
    float4 v = src[i];
    dst[i*2]   = __floats2half2_rn(v.x, v.y);
    dst[i*2+1] = __floats2half2_rn(v.z, v.w);
}

__global__ __launch_bounds__(256)
void conv3_kernel(const float4* __restrict__ s0, const float4* __restrict__ s1,
                  const float4* __restrict__ s2, __half2* __restrict__ dst, int n4each)
{
    int i = blockIdx.x * 256 + threadIdx.x;
    if (i >= 3 * n4each) return;
    int sel = i / n4each, r = i - sel * n4each;
    const float4* src = (sel == 0) ? s0 : (sel == 1) ? s1 : s2;
    float4 v = src[r];
    dst[i*2]   = __floats2half2_rn(v.x, v.y);
    dst[i*2+1] = __floats2half2_rn(v.z, v.w);
}

__global__ __launch_bounds__(256)
void embed_kernel(const int* __restrict__ idx, const float* __restrict__ tok,
                  const float* __restrict__ pos, float* __restrict__ x)
{
    long long i = (long long)blockIdx.x * 256 + threadIdx.x;
    if (i >= (long long)M_ * E_) return;
    int e = (int)(i % E_);
    long long bt = i / E_;
    int t = (int)(bt % T_);
    x[i] = tok[(long long)idx[bt] * E_ + e] + pos[(long long)t * E_ + e];
}

__global__ __launch_bounds__(256)
void layernorm_kernel(const float* __restrict__ x, const float* __restrict__ g,
                      const float* __restrict__ b, fp16* __restrict__ oh)
{
    int row = blockIdx.x;
    const float* xr = x + (long long)row * E_;
    int tid = threadIdx.x;
    float s = 0.f, s2 = 0.f;
    for (int e = tid; e < E_; e += 256) { float v = xr[e]; s += v; s2 += v * v; }
    #pragma unroll
    for (int off = 16; off; off >>= 1) {
        s  += __shfl_xor_sync(0xffffffffu, s,  off);
        s2 += __shfl_xor_sync(0xffffffffu, s2, off);
    }
    __shared__ float rs[8], rs2[8];
    if ((tid & 31) == 0) { rs[tid >> 5] = s; rs2[tid >> 5] = s2; }
    __syncthreads();
    float S = 0.f, S2 = 0.f;
    #pragma unroll
    for (int i = 0; i < 8; i++) { S += rs[i]; S2 += rs2[i]; }
    float mean = S * (1.f / E_);
    float rstd = rsqrtf(S2 * (1.f / E_) - mean * mean + 1e-5f);
    for (int e = tid; e < E_; e += 256) {
        float y = (xr[e] - mean) * rstd * g[e] + b[e];
        oh[(long long)row * E_ + e] = __float2half_rn(y);
    }
}

// fused: x += bias + p0+p1+p2 (write back), then LN(x) -> oh
__global__ __launch_bounds__(256)
void reduce3_ln_kernel(float* __restrict__ x, const float* __restrict__ p,
                       const float* __restrict__ bias,
                       const float* __restrict__ g, const float* __restrict__ b,
                       fp16* __restrict__ oh)
{
    const long long NE = (long long)M_ * E_;
    int row = blockIdx.x;
    long long base = (long long)row * E_;
    int tid = threadIdx.x;
    float y[3];
    float s = 0.f, s2 = 0.f;
    #pragma unroll
    for (int i = 0; i < 3; i++) {
        int e = tid + i * 256;
        float v = x[base + e] + bias[e] + p[base + e] + p[NE + base + e] + p[2 * NE + base + e];
        y[i] = v; s += v; s2 += v * v;
        x[base + e] = v;
    }
    #pragma unroll
    for (int off = 16; off; off >>= 1) {
        s  += __shfl_xor_sync(0xffffffffu, s,  off);
        s2 += __shfl_xor_sync(0xffffffffu, s2, off);
    }
    __shared__ float rs[8], rs2[8];
    if ((tid & 31) == 0) { rs[tid >> 5] = s; rs2[tid >> 5] = s2; }
    __syncthreads();
    float S = 0.f, S2 = 0.f;
    #pragma unroll
    for (int i = 0; i < 8; i++) { S += rs[i]; S2 += rs2[i]; }
    float mean = S * (1.f / E_);
    float rstd = rsqrtf(S2 * (1.f / E_) - mean * mean + 1e-5f);
    #pragma unroll
    for (int i = 0; i < 3; i++) {
        int e = tid + i * 256;
        oh[base + e] = __float2half_rn((y[i] - mean) * rstd * g[e] + b[e]);
    }
}

__global__ __launch_bounds__(256)
void transpose_vT(const fp16* __restrict__ v, fp16* __restrict__ vt)
{
    int bh = blockIdx.y;
    int b = bh / H_, h = bh % H_;
    int t0 = blockIdx.x * 64;
    int tid = threadIdx.x;
    __shared__ fp16 tile[64][65];
    #pragma unroll
    for (int i = 0; i < 16; i++) {
        int id = tid + i * 256;
        int r = id >> 6, c = id & 63;
        tile[r][c] = v[(long long)(b * T_ + t0 + r) * E_ + h * DH_ + c];
    }
    __syncthreads();
    #pragma unroll
    for (int i = 0; i < 16; i++) {
        int id = tid + i * 256;
        int d = id >> 6, tc = id & 63;
        vt[(long long)(bh * DH_ + d) * T_ + t0 + tc] = tile[tc][d];
    }
}

// ========================= 128x128 fp16 GEMM, k-chunk 64, 2-stage, occ 2 =========================
#define G_RS   144
#define G_APL  (128*G_RS)
#define G_SSTR (2*G_APL)
#define G_SMEM (2 * G_SSTR)     // 73728

__device__ __forceinline__ void issue_stage(
    uint32_t sb, int stage, int c,
    const fp16* A, int lda, int m0,
    const fp16* Bm, int ldb, int n0, int tid)
{
    uint32_t base = sb + stage * G_SSTR;
    int k0 = c * 64;
    #pragma unroll
    for (int i = 0; i < 4; i++) {
        int id = tid + i * 256;
        int row = id >> 3, kq = id & 7;
        const fp16* src = A + (long long)(m0 + row) * lda + k0 + kq * 8;
        CP_ASYNC16(base + row * G_RS + kq * 16, src);
    }
    #pragma unroll
    for (int i = 0; i < 4; i++) {
        int id = tid + i * 256;
        int row = id >> 3, kq = id & 7;
        const fp16* src = Bm + (long long)(n0 + row) * ldb + k0 + kq * 8;
        CP_ASYNC16(base + G_APL + row * G_RS + kq * 16, src);
    }
}

__global__ __launch_bounds__(256, 2)
void gemm_mma(const fp16* __restrict__ A, int lda,
              const fp16* __restrict__ Bm, int ldb,
              float* outF,
              fp16* o0, fp16* o1, fp16* o2, int nRoute, float qscale,
              int ldc,
              const float* __restrict__ bias, const float* __restrict__ resid,
              int relu, int K, int zK, long long zC)
{
    extern __shared__ char smem[];
    uint32_t sb = smem_u32(smem);

    int tid = threadIdx.x, wid = tid >> 5, lane = tid & 31;
    int m0 = blockIdx.y * 128;
    int n0 = blockIdx.x * 128;
    int z = blockIdx.z;
    A  += (long long)z * zK;
    Bm += (long long)z * zK;
    long long cBase = (long long)z * zC;
    int nc = K / 64;

    issue_stage(sb, 0, 0, A, lda, m0, Bm, ldb, n0, tid);
    CP_COMMIT();
    issue_stage(sb, 1, 1, A, lda, m0, Bm, ldb, n0, tid);
    CP_COMMIT();

    int wm = (wid >> 2) * 64, wn = (wid & 3) * 32;
    int rq = lane & 15;

    float acc[4][4][4];
    #pragma unroll
    for (int a = 0; a < 4; a++)
        #pragma unroll
        for (int b = 0; b < 4; b++)
            #pragma unroll
            for (int c = 0; c < 4; c++) acc[a][b][c] = 0.f;

    for (int c = 0; c < nc; c++) {
        CP_WAIT1();
        __syncthreads();
        uint32_t base = sb + (c & 1) * G_SSTR;
        #pragma unroll
        for (int ks = 0; ks < 4; ks++) {
            int colb = (ks * 16 + (lane >> 4) * 8) * 2;
            uint32_t ahf[4][4];
            #pragma unroll
            for (int mi = 0; mi < 4; mi++) {
                uint32_t addr = base + (wm + mi * 16 + rq) * G_RS + colb;
                LDSM4(ahf[mi], addr);
            }
            #pragma unroll
            for (int bj = 0; bj < 2; bj++) {
                uint32_t bhf[4];
                uint32_t addr = base + G_APL + (wn + bj * 16 + rq) * G_RS + colb;
                LDSM4(bhf, addr);
                #pragma unroll
                for (int mi = 0; mi < 4; mi++)
                    #pragma unroll
                    for (int hf = 0; hf < 2; hf++)
                        MMA_FP16(acc[mi][bj * 2 + hf], ahf[mi], bhf[hf], bhf[hf + 2]);
            }
        }
        __syncthreads();
        if (c + 2 < nc) {
            issue_stage(sb, c & 1, c + 2, A, lda, m0, Bm, ldb, n0, tid);
        }
        CP_COMMIT();
    }

    fp16 *OH = o0;
    int coff = 0;
    float osc = 1.f;
    if (nRoute) {
        int sel = n0 / nRoute;
        coff = sel * nRoute;
        if (sel == 0) osc = qscale;
        else if (sel == 1) OH = o1;
        else OH = o2;
    }
    #pragma unroll
    for (int mi = 0; mi < 4; mi++) {
        #pragma unroll
        for (int nf = 0; nf < 4; nf++) {
            int col = n0 + wn + nf * 8 + (lane & 3) * 2;
            #pragma unroll
            for (int hf = 0; hf < 2; hf++) {
                int row = m0 + wm + mi * 16 + (lane >> 2) + hf * 8;
                float v0 = acc[mi][nf][hf * 2], v1 = acc[mi][nf][hf * 2 + 1];
                if (bias) { v0 += __ldg(bias + col); v1 += __ldg(bias + col + 1); }
                if (relu) { v0 = fmaxf(v0, 0.f); v1 = fmaxf(v1, 0.f); }
                v0 *= osc; v1 *= osc;
                long long off = cBase + (long long)row * ldc + (col - coff);
                if (resid) { float2 r = *(const float2*)(resid + off); v0 += r.x; v1 += r.y; }
                if (outF) { float2 ov; ov.x = v0; ov.y = v1; *(float2*)(outF + off) = ov; }
                if (OH) *(uint32_t*)(OH + off) = f2h2(v0, v1);
            }
        }
    }
}

// ========================= persistent LM head GEMM =========================
// grid (16, 18); each CTA loops n-tiles nt0, nt0+18, ... keeping the cp.async
// pipeline full across tile boundaries.
#define HD_NC   (E_/64)     // 12
#define HD_NSP  18
#define HD_NT   (V_/128)    // 250

__global__ __launch_bounds__(256, 2)
void gemm_head(const fp16* __restrict__ A, const fp16* __restrict__ Bm,
               float* __restrict__ outF, const float* __restrict__ bias)
{
    extern __shared__ char smem[];
    uint32_t sb = smem_u32(smem);
    int tid = threadIdx.x, wid = tid >> 5, lane = tid & 31;
    int m0 = blockIdx.x * 128;
    int nt0 = blockIdx.y;
    int nTiles = (HD_NT - nt0 + HD_NSP - 1) / HD_NSP;
    int total = nTiles * HD_NC;

    // issue for global step g
    auto n0_of = [&](int g) { return (nt0 + (g / HD_NC) * HD_NSP) * 128; };

    issue_stage(sb, 0, 0, A, E_, m0, Bm, E_, n0_of(0), tid);
    CP_COMMIT();
    if (total > 1) issue_stage(sb, 1, 1 % HD_NC, A, E_, m0, Bm, E_, n0_of(1), tid);
    CP_COMMIT();

    int wm = (wid >> 2) * 64, wn = (wid & 3) * 32;
    int rq = lane & 15;

    int g = 0;
    for (int t = 0; t < nTiles; t++) {
        int n0 = (nt0 + t * HD_NSP) * 128;
        float acc[4][4][4];
        #pragma unroll
        for (int a = 0; a < 4; a++)
            #pragma unroll
            for (int b = 0; b < 4; b++)
                #pragma unroll
                for (int c = 0; c < 4; c++) acc[a][b][c] = 0.f;

        for (int c = 0; c < HD_NC; c++, g++) {
            CP_WAIT1();
            __syncthreads();
            uint32_t base = sb + (g & 1) * G_SSTR;
            #pragma unroll
            for (int ks = 0; ks < 4; ks++) {
                int colb = (ks * 16 + (lane >> 4) * 8) * 2;
                uint32_t ahf[4][4];
                #pragma unroll
                for (int mi = 0; mi < 4; mi++) {
                    uint32_t addr = base + (wm + mi * 16 + rq) * G_RS + colb;
                    LDSM4(ahf[mi], addr);
                }
                #pragma unroll
                for (int bj = 0; bj < 2; bj++) {
                    uint32_t bhf[4];
                    uint32_t addr = base + G_APL + (wn + bj * 16 + rq) * G_RS + colb;
                    LDSM4(bhf, addr);
                    #pragma unroll
                    for (int mi = 0; mi < 4; mi++)
                        #pragma unroll
                        for (int hf = 0; hf < 2; hf++)
                            MMA_FP16(acc[mi][bj * 2 + hf], ahf[mi], bhf[hf], bhf[hf + 2]);
                }
            }
            __syncthreads();
            if (g + 2 < total) {
                int g2 = g + 2;
                issue_stage(sb, g & 1, g2 % HD_NC, A, E_, m0, Bm, E_, n0_of(g2), tid);
            }
            CP_COMMIT();
        }

        // epilogue for (m0, n0)
        #pragma unroll
        for (int mi = 0; mi < 4; mi++) {
            #pragma unroll
            for (int nf = 0; nf < 4; nf++) {
                int col = n0 + wn + nf * 8 + (lane & 3) * 2;
                #pragma unroll
                for (int hf = 0; hf < 2; hf++) {
                    int row = m0 + wm + mi * 16 + (lane >> 2) + hf * 8;
                    float v0 = acc[mi][nf][hf * 2] + __ldg(bias + col);
                    float v1 = acc[mi][nf][hf * 2 + 1] + __ldg(bias + col + 1);
                    float2 ov; ov.x = v0; ov.y = v1;
                    *(float2*)(outF + (long long)row * V_ + col) = ov;
                }
            }
        }
    }
}

// ========================= fused flash attention (max-free softmax) =========
#define FA_QS   144
#define FA_QSZ  (128*FA_QS)
#define FA_KOFF FA_QSZ
#define FA_KBUF (128*FA_QS)
#define FA_VOFF (FA_KOFF + 2*FA_KBUF)
#define FA_VS   272
#define FA_VBUF (64*FA_VS)
#define FA_SMEM (FA_VOFF + 2*FA_VBUF)  // 90112

__device__ __forceinline__ void fa_issue_kv(
    uint32_t sb, int buf, int j,
    const fp16* k, const fp16* vt,
    int b, int h, int bh, int tid)
{
    int n0 = j * 128;
    const fp16* kb = k + (long long)(b * T_ + n0) * E_ + h * DH_;
    uint32_t kbm = sb + FA_KOFF + buf * FA_KBUF;
    #pragma unroll
    for (int i = 0; i < 4; i++) {
        int id = tid + i * 256;
        int row = id >> 3, qd = id & 7;
        const fp16* src = kb + (long long)row * E_ + qd * 8;
        CP_ASYNC16(kbm + row * FA_QS + qd * 16, src);
    }
    const fp16* vb = vt + (long long)(bh * DH_) * T_ + n0;
    uint32_t vbm = sb + FA_VOFF + buf * FA_VBUF;
    #pragma unroll
    for (int i = 0; i < 4; i++) {
        int id = tid + i * 256;
        int row = id >> 4, qd = id & 15;
        const fp16* src = vb + (long long)row * T_ + qd * 8;
        CP_ASYNC16(vbm + row * FA_VS + qd * 16, src);
    }
}

__global__ __launch_bounds__(256, 1)
void flash_kernel(const fp16* __restrict__ q,
                  const fp16* __restrict__ k, const fp16* __restrict__ vt,
                  fp16* __restrict__ o)
{
    extern __shared__ char smem[];
    uint32_t sb = smem_u32(smem);
    int tid = threadIdx.x, wid = tid >> 5, lane = tid & 31;
    int bh = blockIdx.z;
    int b = bh / H_, h = bh % H_;
    int mt = (int)gridDim.y - 1 - (int)blockIdx.y;
    int m0 = mt * 128;

    {
        const fp16* qb = q + (long long)(b * T_ + m0) * E_ + h * DH_;
        #pragma unroll
        for (int i = 0; i < 4; i++) {
            int id = tid + i * 256;
            int row = id >> 3, qd = id & 7;
            const fp16* src = qb + (long long)row * E_ + qd * 8;
            CP_ASYNC16(sb + row * FA_QS + qd * 16, src);
        }
        CP_COMMIT();
    }
    fa_issue_kv(sb, 0, 0, k, vt, b, h, bh, tid);
    CP_COMMIT();

    int wr0 = wid * 16;
    int ra = lane >> 2;
    int rq = lane & 15;

    float l_a = 0.f, l_b = 0.f;
    float accO[8][4];
    #pragma unroll
    for (int i = 0; i < 8; i++)
        #pragma unroll
        for (int c = 0; c < 4; c++) accO[i][c] = 0.f;

    for (int j = 0; j <= mt; j++) {
        __syncthreads();
        if (j < mt) {
            fa_issue_kv(sb, (j + 1) & 1, j + 1, k, vt, b, h, bh, tid);
            CP_COMMIT();
            CP_WAIT1();
        } else {
            CP_WAIT0();
        }
        __syncthreads();

        uint32_t kb = sb + FA_KOFF + (j & 1) * FA_KBUF;
        uint32_t vb = sb + FA_VOFF + (j & 1) * FA_VBUF;

        float accS[16][4];
        #pragma unroll
        for (int i = 0; i < 16; i++)
            #pragma unroll
            for (int c = 0; c < 4; c++) accS[i][c] = 0.f;

        #pragma unroll
        for (int ks = 0; ks < 4; ks++) {
            int colb = (ks * 16 + (lane >> 4) * 8) * 2;
            uint32_t ahf[4];
            LDSM4(ahf, sb + (wr0 + rq) * FA_QS + colb);
            #pragma unroll
            for (int bj = 0; bj < 8; bj++) {
                uint32_t bhf[4];
                LDSM4(bhf, kb + (bj * 16 + rq) * FA_QS + colb);
                #pragma unroll
                for (int hf = 0; hf < 2; hf++)
                    MMA_FP16(accS[bj * 2 + hf], ahf, bhf[hf], bhf[hf + 2]);
            }
        }

        // max-free softmax accumulation (q pre-scaled; scores bounded)
        bool diag = (j == mt);
        int rla = wr0 + ra, rlb = rla + 8;
        float suma = 0.f, sumb = 0.f;
        #pragma unroll
        for (int nf = 0; nf < 16; nf++) {
            #pragma unroll
            for (int c2 = 0; c2 < 2; c2++) {
                int cl = nf * 8 + (lane & 3) * 2 + c2;
                float va = accS[nf][c2];
                float vb2 = accS[nf][2 + c2];
                if (diag) {
                    if (cl > rla) va = -1e30f;
                    if (cl > rlb) vb2 = -1e30f;
                }
                float pa = __expf(va);
                float pb = __expf(vb2);
                accS[nf][c2] = pa; accS[nf][2 + c2] = pb;
                suma += pa; sumb += pb;
            }
        }
        suma += __shfl_xor_sync(0xffffffffu, suma, 1);
        suma += __shfl_xor_sync(0xffffffffu, suma, 2);
        sumb += __shfl_xor_sync(0xffffffffu, sumb, 1);
        sumb += __shfl_xor_sync(0xffffffffu, sumb, 2);
        l_a += suma;
        l_b += sumb;

        #pragma unroll
        for (int ks = 0; ks < 8; ks++) {
            uint32_t pah[4];
            pah[0] = f2h2(accS[2 * ks][0],     accS[2 * ks][1]);
            pah[1] = f2h2(accS[2 * ks][2],     accS[2 * ks][3]);
            pah[2] = f2h2(accS[2 * ks + 1][0], accS[2 * ks + 1][1]);
            pah[3] = f2h2(accS[2 * ks + 1][2], accS[2 * ks + 1][3]);
            int colb = (ks * 16 + (lane >> 4) * 8) * 2;
            #pragma unroll
            for (int bj = 0; bj < 4; bj++) {
                uint32_t vhf[4];
                LDSM4(vhf, vb + (bj * 16 + rq) * FA_VS + colb);
                #pragma unroll
                for (int hf = 0; hf < 2; hf++)
                    MMA_FP16(accO[bj * 2 + hf], pah, vhf[hf], vhf[hf + 2]);
            }
        }
    }

    float inva = 1.f / l_a, invb = 1.f / l_b;
    long long rowa = (long long)(b * T_ + m0 + wr0 + ra) * E_ + h * DH_;
    long long rowb = rowa + 8LL * E_;
    int c0 = (lane & 3) * 2;
    #pragma unroll
    for (int nf = 0; nf < 8; nf++) {
        int col = c0 + nf * 8;
        *(uint32_t*)(o + rowa + col) = f2h2(accO[nf][0] * inva, accO[nf][1] * inva);
        *(uint32_t*)(o + rowb + col) = f2h2(accO[nf][2] * invb, accO[nf][3] * invb);
    }
}

// ========================= host =========================
static inline void conv_launch(const float* src, fp16* dst, long long n)
{
    int n4 = (int)(n / 4);
    conv_kernel<<<(n4 + 255) / 256, 256>>>((const float4*)src, (__half2*)dst, n4);
}

extern "C" void kernel_launch(void* const* d_in, const int* in_sizes, int n_in,
                              void* d_out, int out_size)
{
    const int*   idx  = (const int*)  d_in[0];
    const float* tok  = (const float*)d_in[1];
    const float* pos  = (const float*)d_in[2];
    const float* Wq   = (const float*)d_in[3];
    const float* Wk   = (const float*)d_in[4];
    const float* Wv   = (const float*)d_in[5];
    const float* Wo   = (const float*)d_in[6];
    const float* bo   = (const float*)d_in[7];
    const float* ln1g = (const float*)d_in[8];
    const float* ln1b = (const float*)d_in[9];
    const float* W1   = (const float*)d_in[10];
    const float* b1   = (const float*)d_in[11];
    const float* W2   = (const float*)d_in[12];
    const float* b2   = (const float*)d_in[13];
    const float* ln2g = (const float*)d_in[14];
    const float* ln2b = (const float*)d_in[15];
    const float* lnfg = (const float*)d_in[16];
    const float* lnfb = (const float*)d_in[17];
    const float* Wlm  = (const float*)d_in[18];
    const float* blm  = (const float*)d_in[19];
    float* out = (float*)d_out;

    fp16 *wqkv,*wo,*w1,*w2,*wlm;
    fp16 *hA,*qA,*kA,*vA,*vtA,*oA,*ffA;
    float *x, *part;
    cudaGetSymbolAddress((void**)&wqkv, g_wqkv);
    cudaGetSymbolAddress((void**)&wo, g_wo);
    cudaGetSymbolAddress((void**)&w1, g_w1);
    cudaGetSymbolAddress((void**)&w2, g_w2);
    cudaGetSymbolAddress((void**)&wlm, g_wlm);
    cudaGetSymbolAddress((void**)&hA, g_h);
    cudaGetSymbolAddress((void**)&qA, g_q);
    cudaGetSymbolAddress((void**)&kA, g_k);
    cudaGetSymbolAddress((void**)&vA, g_v);
    cudaGetSymbolAddress((void**)&vtA, g_vt);
    cudaGetSymbolAddress((void**)&oA, g_o);
    cudaGetSymbolAddress((void**)&ffA, g_ff);
    cudaGetSymbolAddress((void**)&x, g_x);
    cudaGetSymbolAddress((void**)&part, g_part);

    cudaFuncSetAttribute(gemm_mma,  cudaFuncAttributeMaxDynamicSharedMemorySize, G_SMEM);
    cudaFuncSetAttribute(gemm_head, cudaFuncAttributeMaxDynamicSharedMemorySize, G_SMEM);
    cudaFuncSetAttribute(flash_kernel, cudaFuncAttributeMaxDynamicSharedMemorySize, FA_SMEM);

    const long long EE = (long long)E_ * E_;
    const long long NE = (long long)M_ * E_;
    const float scale = 1.0f / sqrtf((float)E_);
    int n4e = (int)(EE / 4);

    // launch 0: layer-0 QKV weight convert
    conv3_kernel<<<(3 * n4e + 255) / 256, 256>>>((const float4*)Wq, (const float4*)Wk,
        (const float4*)Wv, (__half2*)wqkv, n4e);
    // launch 1: embed
    embed_kernel<<<(int)(((long long)M_*E_ + 255)/256), 256>>>(idx, tok, pos, x);
    // launch 2: LN1 layer 0
    layernorm_kernel<<<M_, 256>>>(x, ln1g, ln1b, hA);
    // launch 3: layer-0 fused QKV GEMM (ncu target)
    {
        dim3 g(3 * E_ / 128, M_ / 128, 1);
        gemm_mma<<<g, 256, G_SMEM>>>(hA, E_, wqkv, E_,
            nullptr, qA, kA, vA, E_, scale,
            E_, nullptr, nullptr, 0, E_, 0, 0);
    }

    // remaining weight converts
    for (int l = 1; l < L_; l++)
        conv3_kernel<<<(3 * n4e + 255) / 256, 256>>>(
            (const float4*)(Wq + l * EE), (const float4*)(Wk + l * EE), (const float4*)(Wv + l * EE),
            (__half2*)(wqkv + l * 3 * EE), n4e);
    conv_launch(Wo, wo, (long long)L_*E_*E_);
    conv_launch(W1, w1, (long long)L_*DF_*E_);
    conv_launch(W2, w2, (long long)L_*E_*DF_);
    conv_launch(Wlm, wlm, (long long)V_*E_);

    for (int l = 0; l < L_; l++) {
        if (l > 0) {
            dim3 g(3 * E_ / 128, M_ / 128, 1);
            gemm_mma<<<g, 256, G_SMEM>>>(hA, E_,
                wqkv + l * 3 * EE, E_,
                nullptr, qA, kA, vA, E_, scale,
                E_, nullptr, nullptr, 0, E_, 0, 0);
        }

        {
            dim3 g(T_/64, B_*H_);
            transpose_vT<<<g, 256>>>(vA, vtA);
        }
        {
            dim3 g(1, T_/128, B_*H_);
            flash_kernel<<<g, 256, FA_SMEM>>>(qA, kA, vtA, oA);
        }

        // Wo: split-K=3 (KS=256) -> partials, fused reduce+LN2 -> hA
        {
            dim3 g(E_/128, M_/128, 3);
            gemm_mma<<<g, 256, G_SMEM>>>(oA, E_, wo + l*EE, E_,
                part, nullptr, nullptr, nullptr, 0, 1.f,
                E_, nullptr, nullptr, 0, 256, 256, NE);
            reduce3_ln_kernel<<<M_, 256>>>(x, part, bo + l*E_, ln2g + l*E_, ln2b + l*E_, hA);
        }

        // ff = relu(h @ W1^T + b1)
        {
            dim3 g(DF_/128, M_/128, 1);
            gemm_mma<<<g, 256, G_SMEM>>>(hA, E_,
                w1 + (long long)l*DF_*E_, E_,
                nullptr, ffA, nullptr, nullptr, 0, 1.f,
                DF_, b1 + l*DF_, nullptr, 1, E_, 0, 0);
        }
        // FFN2: split-K=3 (KS=1024) -> partials, fused reduce + next LN -> hA
        {
            dim3 g(E_/128, M_/128, 3);
            gemm_mma<<<g, 256, G_SMEM>>>(ffA, DF_,
                w2 + (long long)l*E_*DF_, DF_,
                part, nullptr, nullptr, nullptr, 0, 1.f,
                E_, nullptr, nullptr, 0, 1024, 1024, NE);
            const float* ng = (l + 1 < L_) ? ln1g + (l+1)*E_ : lnfg;
            const float* nb = (l + 1 < L_) ? ln1b + (l+1)*E_ : lnfb;
            reduce3_ln_kernel<<<M_, 256>>>(x, part, b2 + l*E_, ng, nb, hA);
        }
    }

    // persistent LM head
    {
        dim3 g(M_/128, HD_NSP, 1);
        gemm_head<<<g, 256, G_SMEM>>>(hA, wlm, out, blm);
    }
}

// round 15
// speedup vs baseline: 1.0331x; 1.0331x over previous
#include <cuda_runtime.h>
#include <cuda_fp16.h>
#include <cstdint>
#include <math.h>

#define B_  2
#define T_  1024
#define E_  768
#define H_  12
#define L_  6
#define V_  32000
#define DH_ 64
#define DF_ 3072
#define M_  (B_*T_)

typedef __half fp16;

// ========================= helpers =========================
__device__ __forceinline__ uint32_t smem_u32(const void* p) {
    uint32_t a;
    asm("{ .reg .u64 t; cvta.to.shared.u64 t, %1; cvt.u32.u64 %0, t; }" : "=r"(a) : "l"(p));
    return a;
}
#define LDSM4(r, addr) \
    asm volatile("ldmatrix.sync.aligned.m8n8.x4.shared.b16 {%0,%1,%2,%3}, [%4];" \
        : "=r"((r)[0]), "=r"((r)[1]), "=r"((r)[2]), "=r"((r)[3]) : "r"(addr))
#define MMA_FP16(d, a, b0, b1) \
    asm volatile("mma.sync.aligned.m16n8k16.row.col.f32.f16.f16.f32 " \
        "{%0,%1,%2,%3}, {%4,%5,%6,%7}, {%8,%9}, {%0,%1,%2,%3};" \
        : "+f"((d)[0]), "+f"((d)[1]), "+f"((d)[2]), "+f"((d)[3]) \
        : "r"((a)[0]), "r"((a)[1]), "r"((a)[2]), "r"((a)[3]), "r"(b0), "r"(b1))
#define CP_ASYNC16(dst, src) \
    asm volatile("cp.async.cg.shared.global [%0], [%1], 16;" :: "r"(dst), "l"(src))
#define CP_COMMIT() asm volatile("cp.async.commit_group;" ::: "memory")
#define CP_WAIT1()  asm volatile("cp.async.wait_group 1;" ::: "memory")
#define CP_WAIT0()  asm volatile("cp.async.wait_group 0;" ::: "memory")

__device__ __forceinline__ uint32_t f2h2(float x, float y) {
    __half2 h = __floats2half2_rn(x, y);
    return *(uint32_t*)&h;
}

// ========================= device scratch (single fp16 planes) =========================
__device__ fp16 g_wqkv[L_*3*E_*E_];
__device__ fp16 g_wo[L_*E_*E_];
__device__ fp16 g_w1[L_*DF_*E_];
__device__ fp16 g_w2[L_*E_*DF_];
__device__ fp16 g_wlm[V_*E_];
__device__ fp16 g_h[M_*E_];
__device__ fp16 g_q[M_*E_];
__device__ fp16 g_k[M_*E_];
__device__ fp16 g_vt[M_*E_];
__device__ fp16 g_o[M_*E_];
__device__ fp16 g_ff[M_*DF_];
__device__ float g_x[M_*E_];
__device__ float g_part[3LL*M_*E_];

// ========================= small kernels =========================
__global__ __launch_bounds__(256)
void conv_kernel(const float4* __restrict__ src, __half2* __restrict__ dst, int n4)
{
    int i = blockIdx.x * 256 + threadIdx.x;
    if (i >= n4) return;
    float4 v = src[i];
    dst[i*2]   = __floats2half2_rn(v.x, v.y);
    dst[i*2+1] = __floats2half2_rn(v.z, v.w);
}

__global__ __launch_bounds__(256)
void conv3_kernel(const float4* __restrict__ s0, const float4* __restrict__ s1,
                  const float4* __restrict__ s2, __half2* __restrict__ dst, int n4each)
{
    int i = blockIdx.x * 256 + threadIdx.x;
    if (i >= 3 * n4each) return;
    int sel = i / n4each, r = i - sel * n4each;
    const float4* src = (sel == 0) ? s0 : (sel == 1) ? s1 : s2;
    float4 v = src[r];
    dst[i*2]   = __floats2half2_rn(v.x, v.y);
    dst[i*2+1] = __floats2half2_rn(v.z, v.w);
}

__global__ __launch_bounds__(256)
void embed_kernel(const int* __restrict__ idx, const float* __restrict__ tok,
                  const float* __restrict__ pos, float* __restrict__ x)
{
    long long i = (long long)blockIdx.x * 256 + threadIdx.x;
    if (i >= (long long)M_ * E_) return;
    int e = (int)(i % E_);
    long long bt = i / E_;
    int t = (int)(bt % T_);
    x[i] = tok[(long long)idx[bt] * E_ + e] + pos[(long long)t * E_ + e];
}

__global__ __launch_bounds__(256)
void layernorm_kernel(const float* __restrict__ x, const float* __restrict__ g,
                      const float* __restrict__ b, fp16* __restrict__ oh)
{
    int row = blockIdx.x;
    const float* xr = x + (long long)row * E_;
    int tid = threadIdx.x;
    float s = 0.f, s2 = 0.f;
    for (int e = tid; e < E_; e += 256) { float v = xr[e]; s += v; s2 += v * v; }
    #pragma unroll
    for (int off = 16; off; off >>= 1) {
        s  += __shfl_xor_sync(0xffffffffu, s,  off);
        s2 += __shfl_xor_sync(0xffffffffu, s2, off);
    }
    __shared__ float rs[8], rs2[8];
    if ((tid & 31) == 0) { rs[tid >> 5] = s; rs2[tid >> 5] = s2; }
    __syncthreads();
    float S = 0.f, S2 = 0.f;
    #pragma unroll
    for (int i = 0; i < 8; i++) { S += rs[i]; S2 += rs2[i]; }
    float mean = S * (1.f / E_);
    float rstd = rsqrtf(S2 * (1.f / E_) - mean * mean + 1e-5f);
    for (int e = tid; e < E_; e += 256) {
        float y = (xr[e] - mean) * rstd * g[e] + b[e];
        oh[(long long)row * E_ + e] = __float2half_rn(y);
    }
}

// fused: x += bias + p0+p1+p2 (write back), then LN(x) -> oh
__global__ __launch_bounds__(256)
void reduce3_ln_kernel(float* __restrict__ x, const float* __restrict__ p,
                       const float* __restrict__ bias,
                       const float* __restrict__ g, const float* __restrict__ b,
                       fp16* __restrict__ oh)
{
    const long long NE = (long long)M_ * E_;
    int row = blockIdx.x;
    long long base = (long long)row * E_;
    int tid = threadIdx.x;
    float y[3];
    float s = 0.f, s2 = 0.f;
    #pragma unroll
    for (int i = 0; i < 3; i++) {
        int e = tid + i * 256;
        float v = x[base + e] + bias[e] + p[base + e] + p[NE + base + e] + p[2 * NE + base + e];
        y[i] = v; s += v; s2 += v * v;
        x[base + e] = v;
    }
    #pragma unroll
    for (int off = 16; off; off >>= 1) {
        s  += __shfl_xor_sync(0xffffffffu, s,  off);
        s2 += __shfl_xor_sync(0xffffffffu, s2, off);
    }
    __shared__ float rs[8], rs2[8];
    if ((tid & 31) == 0) { rs[tid >> 5] = s; rs2[tid >> 5] = s2; }
    __syncthreads();
    float S = 0.f, S2 = 0.f;
    #pragma unroll
    for (int i = 0; i < 8; i++) { S += rs[i]; S2 += rs2[i]; }
    float mean = S * (1.f / E_);
    float rstd = rsqrtf(S2 * (1.f / E_) - mean * mean + 1e-5f);
    #pragma unroll
    for (int i = 0; i < 3; i++) {
        int e = tid + i * 256;
        oh[base + e] = __float2half_rn((y[i] - mean) * rstd * g[e] + b[e]);
    }
}

// ========================= 128x128 fp16 GEMM, k-chunk 64, 2-stage, occ 2 =========================
#define G_RS   144
#define G_APL  (128*G_RS)
#define G_SSTR (2*G_APL)
#define G_SMEM (2 * G_SSTR)     // 73728

__device__ __forceinline__ void issue_stage(
    uint32_t sb, int stage, int c,
    const fp16* A, int lda, int m0,
    const fp16* Bm, int ldb, int n0, int tid)
{
    uint32_t base = sb + stage * G_SSTR;
    int k0 = c * 64;
    #pragma unroll
    for (int i = 0; i < 4; i++) {
        int id = tid + i * 256;
        int row = id >> 3, kq = id & 7;
        const fp16* src = A + (long long)(m0 + row) * lda + k0 + kq * 8;
        CP_ASYNC16(base + row * G_RS + kq * 16, src);
    }
    #pragma unroll
    for (int i = 0; i < 4; i++) {
        int id = tid + i * 256;
        int row = id >> 3, kq = id & 7;
        const fp16* src = Bm + (long long)(n0 + row) * ldb + k0 + kq * 8;
        CP_ASYNC16(base + G_APL + row * G_RS + kq * 16, src);
    }
}

// SWAP=1: blockIdx.x indexes M (LM head rasterization).
// QKV mode (nRoute=E_): sel 0 -> q (scaled by qscale), sel 1 -> k, sel 2 -> V written TRANSPOSED into vt[b,h,d,t].
template<int SWAP>
__global__ __launch_bounds__(256, 2)
void gemm_mma(const fp16* __restrict__ A, int lda,
              const fp16* __restrict__ Bm, int ldb,
              float* outF,
              fp16* o0, fp16* o1, fp16* vt, int nRoute, float qscale,
              int ldc,
              const float* __restrict__ bias, const float* __restrict__ resid,
              int relu, int K, int zK, long long zC)
{
    extern __shared__ char smem[];
    uint32_t sb = smem_u32(smem);

    int tid = threadIdx.x, wid = tid >> 5, lane = tid & 31;
    int m0 = SWAP ? blockIdx.x * 128 : blockIdx.y * 128;
    int n0 = SWAP ? blockIdx.y * 128 : blockIdx.x * 128;
    int z = blockIdx.z;
    A  += (long long)z * zK;
    Bm += (long long)z * zK;
    long long cBase = (long long)z * zC;
    int nc = K / 64;

    issue_stage(sb, 0, 0, A, lda, m0, Bm, ldb, n0, tid);
    CP_COMMIT();
    issue_stage(sb, 1, 1, A, lda, m0, Bm, ldb, n0, tid);
    CP_COMMIT();

    int wm = (wid >> 2) * 64, wn = (wid & 3) * 32;
    int rq = lane & 15;

    float acc[4][4][4];
    #pragma unroll
    for (int a = 0; a < 4; a++)
        #pragma unroll
        for (int b = 0; b < 4; b++)
            #pragma unroll
            for (int c = 0; c < 4; c++) acc[a][b][c] = 0.f;

    for (int c = 0; c < nc; c++) {
        CP_WAIT1();
        __syncthreads();
        uint32_t base = sb + (c & 1) * G_SSTR;
        #pragma unroll
        for (int ks = 0; ks < 4; ks++) {
            int colb = (ks * 16 + (lane >> 4) * 8) * 2;
            uint32_t ahf[4][4];
            #pragma unroll
            for (int mi = 0; mi < 4; mi++) {
                uint32_t addr = base + (wm + mi * 16 + rq) * G_RS + colb;
                LDSM4(ahf[mi], addr);
            }
            #pragma unroll
            for (int bj = 0; bj < 2; bj++) {
                uint32_t bhf[4];
                uint32_t addr = base + G_APL + (wn + bj * 16 + rq) * G_RS + colb;
                LDSM4(bhf, addr);
                #pragma unroll
                for (int mi = 0; mi < 4; mi++)
                    #pragma unroll
                    for (int hf = 0; hf < 2; hf++)
                        MMA_FP16(acc[mi][bj * 2 + hf], ahf[mi], bhf[hf], bhf[hf + 2]);
            }
        }
        __syncthreads();
        if (c + 2 < nc) {
            issue_stage(sb, c & 1, c + 2, A, lda, m0, Bm, ldb, n0, tid);
        }
        CP_COMMIT();
    }

    fp16 *OH = o0;
    int coff = 0, sel = 0;
    float osc = 1.f;
    if (nRoute) {
        sel = n0 / nRoute;
        coff = sel * nRoute;
        if (sel == 0) osc = qscale;
        else if (sel == 1) OH = o1;
    }
    #pragma unroll
    for (int mi = 0; mi < 4; mi++) {
        #pragma unroll
        for (int nf = 0; nf < 4; nf++) {
            int col = n0 + wn + nf * 8 + (lane & 3) * 2;
            #pragma unroll
            for (int hf = 0; hf < 2; hf++) {
                int row = m0 + wm + mi * 16 + (lane >> 2) + hf * 8;
                float v0 = acc[mi][nf][hf * 2], v1 = acc[mi][nf][hf * 2 + 1];
                if (bias) { v0 += __ldg(bias + col); v1 += __ldg(bias + col + 1); }
                if (relu) { v0 = fmaxf(v0, 0.f); v1 = fmaxf(v1, 0.f); }
                v0 *= osc; v1 *= osc;
                if (nRoute && sel == 2) {
                    // V route: write transposed into vt[((b*H+h)*DH + d)*T + t]
                    int vcol = col - coff;
                    int hh = vcol / DH_, d = vcol % DH_;
                    int bb = row / T_, t = row % T_;
                    long long oidx = ((long long)(bb * H_ + hh) * DH_ + d) * T_ + t;
                    vt[oidx]       = __float2half_rn(v0);
                    vt[oidx + T_]  = __float2half_rn(v1);
                } else {
                    long long off = cBase + (long long)row * ldc + (col - coff);
                    if (resid) { float2 r = *(const float2*)(resid + off); v0 += r.x; v1 += r.y; }
                    if (outF) { float2 ov; ov.x = v0; ov.y = v1; *(float2*)(outF + off) = ov; }
                    if (OH) *(uint32_t*)(OH + off) = f2h2(v0, v1);
                }
            }
        }
    }
}

// ========================= fused flash attention (max-free softmax, occ 1) =========
#define FA_QS   144
#define FA_QSZ  (128*FA_QS)
#define FA_KOFF FA_QSZ
#define FA_KBUF (128*FA_QS)
#define FA_VOFF (FA_KOFF + 2*FA_KBUF)
#define FA_VS   272
#define FA_VBUF (64*FA_VS)
#define FA_SMEM (FA_VOFF + 2*FA_VBUF)  // 90112

__device__ __forceinline__ void fa_issue_kv(
    uint32_t sb, int buf, int j,
    const fp16* k, const fp16* vt,
    int b, int h, int bh, int tid)
{
    int n0 = j * 128;
    const fp16* kb = k + (long long)(b * T_ + n0) * E_ + h * DH_;
    uint32_t kbm = sb + FA_KOFF + buf * FA_KBUF;
    #pragma unroll
    for (int i = 0; i < 4; i++) {
        int id = tid + i * 256;
        int row = id >> 3, qd = id & 7;
        const fp16* src = kb + (long long)row * E_ + qd * 8;
        CP_ASYNC16(kbm + row * FA_QS + qd * 16, src);
    }
    const fp16* vb = vt + (long long)(bh * DH_) * T_ + n0;
    uint32_t vbm = sb + FA_VOFF + buf * FA_VBUF;
    #pragma unroll
    for (int i = 0; i < 4; i++) {
        int id = tid + i * 256;
        int row = id >> 4, qd = id & 15;
        const fp16* src = vb + (long long)row * T_ + qd * 8;
        CP_ASYNC16(vbm + row * FA_VS + qd * 16, src);
    }
}

__global__ __launch_bounds__(256, 1)
void flash_kernel(const fp16* __restrict__ q,
                  const fp16* __restrict__ k, const fp16* __restrict__ vt,
                  fp16* __restrict__ o)
{
    extern __shared__ char smem[];
    uint32_t sb = smem_u32(smem);
    int tid = threadIdx.x, wid = tid >> 5, lane = tid & 31;
    int bh = blockIdx.z;
    int b = bh / H_, h = bh % H_;
    int mt = (int)gridDim.y - 1 - (int)blockIdx.y;
    int m0 = mt * 128;

    {
        const fp16* qb = q + (long long)(b * T_ + m0) * E_ + h * DH_;
        #pragma unroll
        for (int i = 0; i < 4; i++) {
            int id = tid + i * 256;
            int row = id >> 3, qd = id & 7;
            const fp16* src = qb + (long long)row * E_ + qd * 8;
            CP_ASYNC16(sb + row * FA_QS + qd * 16, src);
        }
        CP_COMMIT();
    }
    fa_issue_kv(sb, 0, 0, k, vt, b, h, bh, tid);
    CP_COMMIT();

    int wr0 = wid * 16;
    int ra = lane >> 2;
    int rq = lane & 15;

    float l_a = 0.f, l_b = 0.f;
    float accO[8][4];
    #pragma unroll
    for (int i = 0; i < 8; i++)
        #pragma unroll
        for (int c = 0; c < 4; c++) accO[i][c] = 0.f;

    for (int j = 0; j <= mt; j++) {
        __syncthreads();
        if (j < mt) {
            fa_issue_kv(sb, (j + 1) & 1, j + 1, k, vt, b, h, bh, tid);
            CP_COMMIT();
            CP_WAIT1();
        } else {
            CP_WAIT0();
        }
        __syncthreads();

        uint32_t kb = sb + FA_KOFF + (j & 1) * FA_KBUF;
        uint32_t vb = sb + FA_VOFF + (j & 1) * FA_VBUF;

        float accS[16][4];
        #pragma unroll
        for (int i = 0; i < 16; i++)
            #pragma unroll
            for (int c = 0; c < 4; c++) accS[i][c] = 0.f;

        #pragma unroll
        for (int ks = 0; ks < 4; ks++) {
            int colb = (ks * 16 + (lane >> 4) * 8) * 2;
            uint32_t ahf[4];
            LDSM4(ahf, sb + (wr0 + rq) * FA_QS + colb);
            #pragma unroll
            for (int bj = 0; bj < 8; bj++) {
                uint32_t bhf[4];
                LDSM4(bhf, kb + (bj * 16 + rq) * FA_QS + colb);
                #pragma unroll
                for (int hf = 0; hf < 2; hf++)
                    MMA_FP16(accS[bj * 2 + hf], ahf, bhf[hf], bhf[hf + 2]);
            }
        }

        // max-free softmax accumulation (q pre-scaled; scores bounded)
        bool diag = (j == mt);
        int rla = wr0 + ra, rlb = rla + 8;
        float suma = 0.f, sumb = 0.f;
        #pragma unroll
        for (int nf = 0; nf < 16; nf++) {
            #pragma unroll
            for (int c2 = 0; c2 < 2; c2++) {
                int cl = nf * 8 + (lane & 3) * 2 + c2;
                float va = accS[nf][c2];
                float vb2 = accS[nf][2 + c2];
                if (diag) {
                    if (cl > rla) va = -1e30f;
                    if (cl > rlb) vb2 = -1e30f;
                }
                float pa = __expf(va);
                float pb = __expf(vb2);
                accS[nf][c2] = pa; accS[nf][2 + c2] = pb;
                suma += pa; sumb += pb;
            }
        }
        suma += __shfl_xor_sync(0xffffffffu, suma, 1);
        suma += __shfl_xor_sync(0xffffffffu, suma, 2);
        sumb += __shfl_xor_sync(0xffffffffu, sumb, 1);
        sumb += __shfl_xor_sync(0xffffffffu, sumb, 2);
        l_a += suma;
        l_b += sumb;

        #pragma unroll
        for (int ks = 0; ks < 8; ks++) {
            uint32_t pah[4];
            pah[0] = f2h2(accS[2 * ks][0],     accS[2 * ks][1]);
            pah[1] = f2h2(accS[2 * ks][2],     accS[2 * ks][3]);
            pah[2] = f2h2(accS[2 * ks + 1][0], accS[2 * ks + 1][1]);
            pah[3] = f2h2(accS[2 * ks + 1][2], accS[2 * ks + 1][3]);
            int colb = (ks * 16 + (lane >> 4) * 8) * 2;
            #pragma unroll
            for (int bj = 0; bj < 4; bj++) {
                uint32_t vhf[4];
                LDSM4(vhf, vb + (bj * 16 + rq) * FA_VS + colb);
                #pragma unroll
                for (int hf = 0; hf < 2; hf++)
                    MMA_FP16(accO[bj * 2 + hf], pah, vhf[hf], vhf[hf + 2]);
            }
        }
    }

    float inva = 1.f / l_a, invb = 1.f / l_b;
    long long rowa = (long long)(b * T_ + m0 + wr0 + ra) * E_ + h * DH_;
    long long rowb = rowa + 8LL * E_;
    int c0 = (lane & 3) * 2;
    #pragma unroll
    for (int nf = 0; nf < 8; nf++) {
        int col = c0 + nf * 8;
        *(uint32_t*)(o + rowa + col) = f2h2(accO[nf][0] * inva, accO[nf][1] * inva);
        *(uint32_t*)(o + rowb + col) = f2h2(accO[nf][2] * invb, accO[nf][3] * invb);
    }
}

// ========================= host =========================
static inline void conv_launch(const float* src, fp16* dst, long long n)
{
    int n4 = (int)(n / 4);
    conv_kernel<<<(n4 + 255) / 256, 256>>>((const float4*)src, (__half2*)dst, n4);
}

extern "C" void kernel_launch(void* const* d_in, const int* in_sizes, int n_in,
                              void* d_out, int out_size)
{
    const int*   idx  = (const int*)  d_in[0];
    const float* tok  = (const float*)d_in[1];
    const float* pos  = (const float*)d_in[2];
    const float* Wq   = (const float*)d_in[3];
    const float* Wk   = (const float*)d_in[4];
    const float* Wv   = (const float*)d_in[5];
    const float* Wo   = (const float*)d_in[6];
    const float* bo   = (const float*)d_in[7];
    const float* ln1g = (const float*)d_in[8];
    const float* ln1b = (const float*)d_in[9];
    const float* W1   = (const float*)d_in[10];
    const float* b1   = (const float*)d_in[11];
    const float* W2   = (const float*)d_in[12];
    const float* b2   = (const float*)d_in[13];
    const float* ln2g = (const float*)d_in[14];
    const float* ln2b = (const float*)d_in[15];
    const float* lnfg = (const float*)d_in[16];
    const float* lnfb = (const float*)d_in[17];
    const float* Wlm  = (const float*)d_in[18];
    const float* blm  = (const float*)d_in[19];
    float* out = (float*)d_out;

    fp16 *wqkv,*wo,*w1,*w2,*wlm;
    fp16 *hA,*qA,*kA,*vtA,*oA,*ffA;
    float *x, *part;
    cudaGetSymbolAddress((void**)&wqkv, g_wqkv);
    cudaGetSymbolAddress((void**)&wo, g_wo);
    cudaGetSymbolAddress((void**)&w1, g_w1);
    cudaGetSymbolAddress((void**)&w2, g_w2);
    cudaGetSymbolAddress((void**)&wlm, g_wlm);
    cudaGetSymbolAddress((void**)&hA, g_h);
    cudaGetSymbolAddress((void**)&qA, g_q);
    cudaGetSymbolAddress((void**)&kA, g_k);
    cudaGetSymbolAddress((void**)&vtA, g_vt);
    cudaGetSymbolAddress((void**)&oA, g_o);
    cudaGetSymbolAddress((void**)&ffA, g_ff);
    cudaGetSymbolAddress((void**)&x, g_x);
    cudaGetSymbolAddress((void**)&part, g_part);

    cudaFuncSetAttribute(gemm_mma<0>, cudaFuncAttributeMaxDynamicSharedMemorySize, G_SMEM);
    cudaFuncSetAttribute(gemm_mma<1>, cudaFuncAttributeMaxDynamicSharedMemorySize, G_SMEM);
    cudaFuncSetAttribute(flash_kernel, cudaFuncAttributeMaxDynamicSharedMemorySize, FA_SMEM);

    const long long EE = (long long)E_ * E_;
    const long long NE = (long long)M_ * E_;
    const float scale = 1.0f / sqrtf((float)E_);
    int n4e = (int)(EE / 4);

    // launch 0: layer-0 QKV weight convert
    conv3_kernel<<<(3 * n4e + 255) / 256, 256>>>((const float4*)Wq, (const float4*)Wk,
        (const float4*)Wv, (__half2*)wqkv, n4e);
    // launch 1: embed
    embed_kernel<<<(int)(((long long)M_*E_ + 255)/256), 256>>>(idx, tok, pos, x);
    // launch 2: LN1 layer 0
    layernorm_kernel<<<M_, 256>>>(x, ln1g, ln1b, hA);
    // launch 3: layer-0 fused QKV GEMM (ncu target)
    {
        dim3 g(3 * E_ / 128, M_ / 128, 1);
        gemm_mma<0><<<g, 256, G_SMEM>>>(hA, E_, wqkv, E_,
            nullptr, qA, kA, vtA, E_, scale,
            E_, nullptr, nullptr, 0, E_, 0, 0);
    }

    // remaining weight converts
    for (int l = 1; l < L_; l++)
        conv3_kernel<<<(3 * n4e + 255) / 256, 256>>>(
            (const float4*)(Wq + l * EE), (const float4*)(Wk + l * EE), (const float4*)(Wv + l * EE),
            (__half2*)(wqkv + l * 3 * EE), n4e);
    conv_launch(Wo, wo, (long long)L_*E_*E_);
    conv_launch(W1, w1, (long long)L_*DF_*E_);
    conv_launch(W2, w2, (long long)L_*E_*DF_);
    conv_launch(Wlm, wlm, (long long)V_*E_);

    for (int l = 0; l < L_; l++) {
        if (l > 0) {
            dim3 g(3 * E_ / 128, M_ / 128, 1);
            gemm_mma<0><<<g, 256, G_SMEM>>>(hA, E_,
                wqkv + l * 3 * EE, E_,
                nullptr, qA, kA, vtA, E_, scale,
                E_, nullptr, nullptr, 0, E_, 0, 0);
        }

        {
            dim3 g(1, T_/128, B_*H_);
            flash_kernel<<<g, 256, FA_SMEM>>>(qA, kA, vtA, oA);
        }

        // Wo: split-K=3 (KS=256) -> partials, fused reduce+LN2 -> hA
        {
            dim3 g(E_/128, M_/128, 3);
            gemm_mma<0><<<g, 256, G_SMEM>>>(oA, E_, wo + l*EE, E_,
                part, nullptr, nullptr, nullptr, 0, 1.f,
                E_, nullptr, nullptr, 0, 256, 256, NE);
            reduce3_ln_kernel<<<M_, 256>>>(x, part, bo + l*E_, ln2g + l*E_, ln2b + l*E_, hA);
        }

        // ff = relu(h @ W1^T + b1)
        {
            dim3 g(DF_/128, M_/128, 1);
            gemm_mma<0><<<g, 256, G_SMEM>>>(hA, E_,
                w1 + (long long)l*DF_*E_, E_,
                nullptr, ffA, nullptr, nullptr, 0, 1.f,
                DF_, b1 + l*DF_, nullptr, 1, E_, 0, 0);
        }
        // FFN2: split-K=3 (KS=1024) -> partials, fused reduce + next LN -> hA
        {
            dim3 g(E_/128, M_/128, 3);
            gemm_mma<0><<<g, 256, G_SMEM>>>(ffA, DF_,
                w2 + (long long)l*E_*DF_, DF_,
                part, nullptr, nullptr, nullptr, 0, 1.f,
                E_, nullptr, nullptr, 0, 1024, 1024, NE);
            const float* ng = (l + 1 < L_) ? ln1g + (l+1)*E_ : lnfg;
            const float* nb = (l + 1 < L_) ? ln1b + (l+1)*E_ : lnfb;
            reduce3_ln_kernel<<<M_, 256>>>(x, part, b2 + l*E_, ng, nb, hA);
        }
    }

    // LM head: SWAP rasterization (x = M, y = N) so Wlm streams once
    {
        dim3 g(M_/128, V_/128, 1);
        gemm_mma<1><<<g, 256, G_SMEM>>>(hA, E_, wlm, E_,
            out, nullptr, nullptr, nullptr, 0, 1.f,
            V_, blm, nullptr, 0, E_, 0, 0);
    }
}

// round 16
// speedup vs baseline: 1.0596x; 1.0256x over previous
#include <cuda_runtime.h>
#include <cuda_fp16.h>
#include <cstdint>
#include <math.h>

#define B_  2
#define T_  1024
#define E_  768
#define H_  12
#define L_  6
#define V_  32000
#define DH_ 64
#define DF_ 3072
#define M_  (B_*T_)

typedef __half fp16;

// ========================= helpers =========================
__device__ __forceinline__ uint32_t smem_u32(const void* p) {
    uint32_t a;
    asm("{ .reg .u64 t; cvta.to.shared.u64 t, %1; cvt.u32.u64 %0, t; }" : "=r"(a) : "l"(p));
    return a;
}
#define LDSM4(r, addr) \
    asm volatile("ldmatrix.sync.aligned.m8n8.x4.shared.b16 {%0,%1,%2,%3}, [%4];" \
        : "=r"((r)[0]), "=r"((r)[1]), "=r"((r)[2]), "=r"((r)[3]) : "r"(addr))
#define MMA_FP16(d, a, b0, b1) \
    asm volatile("mma.sync.aligned.m16n8k16.row.col.f32.f16.f16.f32 " \
        "{%0,%1,%2,%3}, {%4,%5,%6,%7}, {%8,%9}, {%0,%1,%2,%3};" \
        : "+f"((d)[0]), "+f"((d)[1]), "+f"((d)[2]), "+f"((d)[3]) \
        : "r"((a)[0]), "r"((a)[1]), "r"((a)[2]), "r"((a)[3]), "r"(b0), "r"(b1))
#define CP_ASYNC16(dst, src) \
    asm volatile("cp.async.cg.shared.global [%0], [%1], 16;" :: "r"(dst), "l"(src))
#define CP_COMMIT() asm volatile("cp.async.commit_group;" ::: "memory")
#define CP_WAIT1()  asm volatile("cp.async.wait_group 1;" ::: "memory")
#define CP_WAIT0()  asm volatile("cp.async.wait_group 0;" ::: "memory")

__device__ __forceinline__ uint32_t f2h2(float x, float y) {
    __half2 h = __floats2half2_rn(x, y);
    return *(uint32_t*)&h;
}

// ========================= device scratch (single fp16 planes) =========================
__device__ fp16 g_wqkv[L_*3*E_*E_];
__device__ fp16 g_wo[L_*E_*E_];
__device__ fp16 g_w1[L_*DF_*E_];
__device__ fp16 g_w2[L_*E_*DF_];
__device__ fp16 g_wlm[V_*E_];
__device__ fp16 g_h[M_*E_];
__device__ fp16 g_q[M_*E_];
__device__ fp16 g_k[M_*E_];
__device__ fp16 g_vt[M_*E_];
__device__ fp16 g_o[M_*E_];
__device__ fp16 g_ff[M_*DF_];
__device__ float g_x[M_*E_];
__device__ float g_part[3LL*M_*E_];

// ========================= small kernels =========================
__global__ __launch_bounds__(256)
void conv_kernel(const float4* __restrict__ src, __half2* __restrict__ dst, int n4)
{
    int i = blockIdx.x * 256 + threadIdx.x;
    if (i >= n4) return;
    float4 v = src[i];
    dst[i*2]   = __floats2half2_rn(v.x, v.y);
    dst[i*2+1] = __floats2half2_rn(v.z, v.w);
}

__global__ __launch_bounds__(256)
void conv3_kernel(const float4* __restrict__ s0, const float4* __restrict__ s1,
                  const float4* __restrict__ s2, __half2* __restrict__ dst, int n4each)
{
    int i = blockIdx.x * 256 + threadIdx.x;
    if (i >= 3 * n4each) return;
    int sel = i / n4each, r = i - sel * n4each;
    const float4* src = (sel == 0) ? s0 : (sel == 1) ? s1 : s2;
    float4 v = src[r];
    dst[i*2]   = __floats2half2_rn(v.x, v.y);
    dst[i*2+1] = __floats2half2_rn(v.z, v.w);
}

__global__ __launch_bounds__(256)
void embed_kernel(const int* __restrict__ idx, const float* __restrict__ tok,
                  const float* __restrict__ pos, float* __restrict__ x)
{
    long long i = (long long)blockIdx.x * 256 + threadIdx.x;
    if (i >= (long long)M_ * E_) return;
    int e = (int)(i % E_);
    long long bt = i / E_;
    int t = (int)(bt % T_);
    x[i] = tok[(long long)idx[bt] * E_ + e] + pos[(long long)t * E_ + e];
}

__global__ __launch_bounds__(256)
void layernorm_kernel(const float* __restrict__ x, const float* __restrict__ g,
                      const float* __restrict__ b, fp16* __restrict__ oh)
{
    int row = blockIdx.x;
    const float* xr = x + (long long)row * E_;
    int tid = threadIdx.x;
    float s = 0.f, s2 = 0.f;
    for (int e = tid; e < E_; e += 256) { float v = xr[e]; s += v; s2 += v * v; }
    #pragma unroll
    for (int off = 16; off; off >>= 1) {
        s  += __shfl_xor_sync(0xffffffffu, s,  off);
        s2 += __shfl_xor_sync(0xffffffffu, s2, off);
    }
    __shared__ float rs[8], rs2[8];
    if ((tid & 31) == 0) { rs[tid >> 5] = s; rs2[tid >> 5] = s2; }
    __syncthreads();
    float S = 0.f, S2 = 0.f;
    #pragma unroll
    for (int i = 0; i < 8; i++) { S += rs[i]; S2 += rs2[i]; }
    float mean = S * (1.f / E_);
    float rstd = rsqrtf(S2 * (1.f / E_) - mean * mean + 1e-5f);
    for (int e = tid; e < E_; e += 256) {
        float y = (xr[e] - mean) * rstd * g[e] + b[e];
        oh[(long long)row * E_ + e] = __float2half_rn(y);
    }
}

// fused: x += bias + p0+p1+p2 (write back), then LN(x) -> oh
__global__ __launch_bounds__(256)
void reduce3_ln_kernel(float* __restrict__ x, const float* __restrict__ p,
                       const float* __restrict__ bias,
                       const float* __restrict__ g, const float* __restrict__ b,
                       fp16* __restrict__ oh)
{
    const long long NE = (long long)M_ * E_;
    int row = blockIdx.x;
    long long base = (long long)row * E_;
    int tid = threadIdx.x;
    float y[3];
    float s = 0.f, s2 = 0.f;
    #pragma unroll
    for (int i = 0; i < 3; i++) {
        int e = tid + i * 256;
        float v = x[base + e] + bias[e] + p[base + e] + p[NE + base + e] + p[2 * NE + base + e];
        y[i] = v; s += v; s2 += v * v;
        x[base + e] = v;
    }
    #pragma unroll
    for (int off = 16; off; off >>= 1) {
        s  += __shfl_xor_sync(0xffffffffu, s,  off);
        s2 += __shfl_xor_sync(0xffffffffu, s2, off);
    }
    __shared__ float rs[8], rs2[8];
    if ((tid & 31) == 0) { rs[tid >> 5] = s; rs2[tid >> 5] = s2; }
    __syncthreads();
    float S = 0.f, S2 = 0.f;
    #pragma unroll
    for (int i = 0; i < 8; i++) { S += rs[i]; S2 += rs2[i]; }
    float mean = S * (1.f / E_);
    float rstd = rsqrtf(S2 * (1.f / E_) - mean * mean + 1e-5f);
    #pragma unroll
    for (int i = 0; i < 3; i++) {
        int e = tid + i * 256;
        oh[base + e] = __float2half_rn((y[i] - mean) * rstd * g[e] + b[e]);
    }
}

// ========================= 128x128 fp16 GEMM, k-chunk 64, 2-stage, occ 2 =========================
// Warp tile 32x64 (4x2 warp grid): per k16 step 2 A-ldsm + 4 B-ldsm feed 16 mma.
#define G_RS   144
#define G_APL  (128*G_RS)
#define G_SSTR (2*G_APL)
#define G_SMEM (2 * G_SSTR)     // 73728

__device__ __forceinline__ void issue_stage(
    uint32_t sb, int stage, int c,
    const fp16* A, int lda, int m0,
    const fp16* Bm, int ldb, int n0, int tid)
{
    uint32_t base = sb + stage * G_SSTR;
    int k0 = c * 64;
    #pragma unroll
    for (int i = 0; i < 4; i++) {
        int id = tid + i * 256;
        int row = id >> 3, kq = id & 7;
        const fp16* src = A + (long long)(m0 + row) * lda + k0 + kq * 8;
        CP_ASYNC16(base + row * G_RS + kq * 16, src);
    }
    #pragma unroll
    for (int i = 0; i < 4; i++) {
        int id = tid + i * 256;
        int row = id >> 3, kq = id & 7;
        const fp16* src = Bm + (long long)(n0 + row) * ldb + k0 + kq * 8;
        CP_ASYNC16(base + G_APL + row * G_RS + kq * 16, src);
    }
}

// SWAP=1: blockIdx.x indexes M (LM head rasterization).
// QKV mode (nRoute=E_): sel 0 -> q (scaled by qscale), sel 1 -> k, sel 2 -> V transposed into vt[b,h,d,t].
template<int SWAP>
__global__ __launch_bounds__(256, 2)
void gemm_mma(const fp16* __restrict__ A, int lda,
              const fp16* __restrict__ Bm, int ldb,
              float* outF,
              fp16* o0, fp16* o1, fp16* vt, int nRoute, float qscale,
              int ldc,
              const float* __restrict__ bias, const float* __restrict__ resid,
              int relu, int K, int zK, long long zC)
{
    extern __shared__ char smem[];
    uint32_t sb = smem_u32(smem);

    int tid = threadIdx.x, wid = tid >> 5, lane = tid & 31;
    int m0 = SWAP ? blockIdx.x * 128 : blockIdx.y * 128;
    int n0 = SWAP ? blockIdx.y * 128 : blockIdx.x * 128;
    int z = blockIdx.z;
    A  += (long long)z * zK;
    Bm += (long long)z * zK;
    long long cBase = (long long)z * zC;
    int nc = K / 64;

    issue_stage(sb, 0, 0, A, lda, m0, Bm, ldb, n0, tid);
    CP_COMMIT();
    issue_stage(sb, 1, 1, A, lda, m0, Bm, ldb, n0, tid);
    CP_COMMIT();

    // 4x2 warp grid: warp tile 32 (M) x 64 (N)
    int wm = (wid & 3) * 32, wn = (wid >> 2) * 64;
    int rq = lane & 15;

    float acc[2][8][4];
    #pragma unroll
    for (int a = 0; a < 2; a++)
        #pragma unroll
        for (int b = 0; b < 8; b++)
            #pragma unroll
            for (int c = 0; c < 4; c++) acc[a][b][c] = 0.f;

    for (int c = 0; c < nc; c++) {
        CP_WAIT1();
        __syncthreads();
        uint32_t base = sb + (c & 1) * G_SSTR;
        #pragma unroll
        for (int ks = 0; ks < 4; ks++) {
            int colb = (ks * 16 + (lane >> 4) * 8) * 2;
            uint32_t ahf[2][4];
            #pragma unroll
            for (int mi = 0; mi < 2; mi++) {
                uint32_t addr = base + (wm + mi * 16 + rq) * G_RS + colb;
                LDSM4(ahf[mi], addr);
            }
            #pragma unroll
            for (int bj = 0; bj < 4; bj++) {
                uint32_t bhf[4];
                uint32_t addr = base + G_APL + (wn + bj * 16 + rq) * G_RS + colb;
                LDSM4(bhf, addr);
                #pragma unroll
                for (int mi = 0; mi < 2; mi++)
                    #pragma unroll
                    for (int hf = 0; hf < 2; hf++)
                        MMA_FP16(acc[mi][bj * 2 + hf], ahf[mi], bhf[hf], bhf[hf + 2]);
            }
        }
        __syncthreads();
        if (c + 2 < nc) {
            issue_stage(sb, c & 1, c + 2, A, lda, m0, Bm, ldb, n0, tid);
        }
        CP_COMMIT();
    }

    fp16 *OH = o0;
    int coff = 0, sel = 0;
    float osc = 1.f;
    if (nRoute) {
        sel = n0 / nRoute;
        coff = sel * nRoute;
        if (sel == 0) osc = qscale;
        else if (sel == 1) OH = o1;
    }
    #pragma unroll
    for (int mi = 0; mi < 2; mi++) {
        #pragma unroll
        for (int nf = 0; nf < 8; nf++) {
            int col = n0 + wn + nf * 8 + (lane & 3) * 2;
            #pragma unroll
            for (int hf = 0; hf < 2; hf++) {
                int row = m0 + wm + mi * 16 + (lane >> 2) + hf * 8;
                float v0 = acc[mi][nf][hf * 2], v1 = acc[mi][nf][hf * 2 + 1];
                if (bias) { v0 += __ldg(bias + col); v1 += __ldg(bias + col + 1); }
                if (relu) { v0 = fmaxf(v0, 0.f); v1 = fmaxf(v1, 0.f); }
                v0 *= osc; v1 *= osc;
                if (nRoute && sel == 2) {
                    int vcol = col - coff;
                    int hh = vcol / DH_, d = vcol % DH_;
                    int bb = row / T_, t = row % T_;
                    long long oidx = ((long long)(bb * H_ + hh) * DH_ + d) * T_ + t;
                    vt[oidx]       = __float2half_rn(v0);
                    vt[oidx + T_]  = __float2half_rn(v1);
                } else {
                    long long off = cBase + (long long)row * ldc + (col - coff);
                    if (resid) { float2 r = *(const float2*)(resid + off); v0 += r.x; v1 += r.y; }
                    if (outF) { float2 ov; ov.x = v0; ov.y = v1; *(float2*)(outF + off) = ov; }
                    if (OH) *(uint32_t*)(OH + off) = f2h2(v0, v1);
                }
            }
        }
    }
}

// ========================= fused flash attention (max-free softmax, occ 1) =========
#define FA_QS   144
#define FA_QSZ  (128*FA_QS)
#define FA_KOFF FA_QSZ
#define FA_KBUF (128*FA_QS)
#define FA_VOFF (FA_KOFF + 2*FA_KBUF)
#define FA_VS   272
#define FA_VBUF (64*FA_VS)
#define FA_SMEM (FA_VOFF + 2*FA_VBUF)  // 90112

__device__ __forceinline__ void fa_issue_kv(
    uint32_t sb, int buf, int j,
    const fp16* k, const fp16* vt,
    int b, int h, int bh, int tid)
{
    int n0 = j * 128;
    const fp16* kb = k + (long long)(b * T_ + n0) * E_ + h * DH_;
    uint32_t kbm = sb + FA_KOFF + buf * FA_KBUF;
    #pragma unroll
    for (int i = 0; i < 4; i++) {
        int id = tid + i * 256;
        int row = id >> 3, qd = id & 7;
        const fp16* src = kb + (long long)row * E_ + qd * 8;
        CP_ASYNC16(kbm + row * FA_QS + qd * 16, src);
    }
    const fp16* vb = vt + (long long)(bh * DH_) * T_ + n0;
    uint32_t vbm = sb + FA_VOFF + buf * FA_VBUF;
    #pragma unroll
    for (int i = 0; i < 4; i++) {
        int id = tid + i * 256;
        int row = id >> 4, qd = id & 15;
        const fp16* src = vb + (long long)row * T_ + qd * 8;
        CP_ASYNC16(vbm + row * FA_VS + qd * 16, src);
    }
}

__global__ __launch_bounds__(256, 1)
void flash_kernel(const fp16* __restrict__ q,
                  const fp16* __restrict__ k, const fp16* __restrict__ vt,
                  fp16* __restrict__ o)
{
    extern __shared__ char smem[];
    uint32_t sb = smem_u32(smem);
    int tid = threadIdx.x, wid = tid >> 5, lane = tid & 31;
    int bh = blockIdx.z;
    int b = bh / H_, h = bh % H_;
    int mt = (int)gridDim.y - 1 - (int)blockIdx.y;
    int m0 = mt * 128;

    {
        const fp16* qb = q + (long long)(b * T_ + m0) * E_ + h * DH_;
        #pragma unroll
        for (int i = 0; i < 4; i++) {
            int id = tid + i * 256;
            int row = id >> 3, qd = id & 7;
            const fp16* src = qb + (long long)row * E_ + qd * 8;
            CP_ASYNC16(sb + row * FA_QS + qd * 16, src);
        }
        CP_COMMIT();
    }
    fa_issue_kv(sb, 0, 0, k, vt, b, h, bh, tid);
    CP_COMMIT();

    int wr0 = wid * 16;
    int ra = lane >> 2;
    int rq = lane & 15;

    float l_a = 0.f, l_b = 0.f;
    float accO[8][4];
    #pragma unroll
    for (int i = 0; i < 8; i++)
        #pragma unroll
        for (int c = 0; c < 4; c++) accO[i][c] = 0.f;

    for (int j = 0; j <= mt; j++) {
        __syncthreads();
        if (j < mt) {
            fa_issue_kv(sb, (j + 1) & 1, j + 1, k, vt, b, h, bh, tid);
            CP_COMMIT();
            CP_WAIT1();
        } else {
            CP_WAIT0();
        }
        __syncthreads();

        uint32_t kb = sb + FA_KOFF + (j & 1) * FA_KBUF;
        uint32_t vb = sb + FA_VOFF + (j & 1) * FA_VBUF;

        float accS[16][4];
        #pragma unroll
        for (int i = 0; i < 16; i++)
            #pragma unroll
            for (int c = 0; c < 4; c++) accS[i][c] = 0.f;

        #pragma unroll
        for (int ks = 0; ks < 4; ks++) {
            int colb = (ks * 16 + (lane >> 4) * 8) * 2;
            uint32_t ahf[4];
            LDSM4(ahf, sb + (wr0 + rq) * FA_QS + colb);
            #pragma unroll
            for (int bj = 0; bj < 8; bj++) {
                uint32_t bhf[4];
                LDSM4(bhf, kb + (bj * 16 + rq) * FA_QS + colb);
                #pragma unroll
                for (int hf = 0; hf < 2; hf++)
                    MMA_FP16(accS[bj * 2 + hf], ahf, bhf[hf], bhf[hf + 2]);
            }
        }

        bool diag = (j == mt);
        int rla = wr0 + ra, rlb = rla + 8;
        float suma = 0.f, sumb = 0.f;
        #pragma unroll
        for (int nf = 0; nf < 16; nf++) {
            #pragma unroll
            for (int c2 = 0; c2 < 2; c2++) {
                int cl = nf * 8 + (lane & 3) * 2 + c2;
                float va = accS[nf][c2];
                float vb2 = accS[nf][2 + c2];
                if (diag) {
                    if (cl > rla) va = -1e30f;
                    if (cl > rlb) vb2 = -1e30f;
                }
                float pa = __expf(va);
                float pb = __expf(vb2);
                accS[nf][c2] = pa; accS[nf][2 + c2] = pb;
                suma += pa; sumb += pb;
            }
        }
        suma += __shfl_xor_sync(0xffffffffu, suma, 1);
        suma += __shfl_xor_sync(0xffffffffu, suma, 2);
        sumb += __shfl_xor_sync(0xffffffffu, sumb, 1);
        sumb += __shfl_xor_sync(0xffffffffu, sumb, 2);
        l_a += suma;
        l_b += sumb;

        #pragma unroll
        for (int ks = 0; ks < 8; ks++) {
            uint32_t pah[4];
            pah[0] = f2h2(accS[2 * ks][0],     accS[2 * ks][1]);
            pah[1] = f2h2(accS[2 * ks][2],     accS[2 * ks][3]);
            pah[2] = f2h2(accS[2 * ks + 1][0], accS[2 * ks + 1][1]);
            pah[3] = f2h2(accS[2 * ks + 1][2], accS[2 * ks + 1][3]);
            int colb = (ks * 16 + (lane >> 4) * 8) * 2;
            #pragma unroll
            for (int bj = 0; bj < 4; bj++) {
                uint32_t vhf[4];
                LDSM4(vhf, vb + (bj * 16 + rq) * FA_VS + colb);
                #pragma unroll
                for (int hf = 0; hf < 2; hf++)
                    MMA_FP16(accO[bj * 2 + hf], pah, vhf[hf], vhf[hf + 2]);
            }
        }
    }

    float inva = 1.f / l_a, invb = 1.f / l_b;
    long long rowa = (long long)(b * T_ + m0 + wr0 + ra) * E_ + h * DH_;
    long long rowb = rowa + 8LL * E_;
    int c0 = (lane & 3) * 2;
    #pragma unroll
    for (int nf = 0; nf < 8; nf++) {
        int col = c0 + nf * 8;
        *(uint32_t*)(o + rowa + col) = f2h2(accO[nf][0] * inva, accO[nf][1] * inva);
        *(uint32_t*)(o + rowb + col) = f2h2(accO[nf][2] * invb, accO[nf][3] * invb);
    }
}

// ========================= host =========================
static inline void conv_launch(const float* src, fp16* dst, long long n)
{
    int n4 = (int)(n / 4);
    conv_kernel<<<(n4 + 255) / 256, 256>>>((const float4*)src, (__half2*)dst, n4);
}

extern "C" void kernel_launch(void* const* d_in, const int* in_sizes, int n_in,
                              void* d_out, int out_size)
{
    const int*   idx  = (const int*)  d_in[0];
    const float* tok  = (const float*)d_in[1];
    const float* pos  = (const float*)d_in[2];
    const float* Wq   = (const float*)d_in[3];
    const float* Wk   = (const float*)d_in[4];
    const float* Wv   = (const float*)d_in[5];
    const float* Wo   = (const float*)d_in[6];
    const float* bo   = (const float*)d_in[7];
    const float* ln1g = (const float*)d_in[8];
    const float* ln1b = (const float*)d_in[9];
    const float* W1   = (const float*)d_in[10];
    const float* b1   = (const float*)d_in[11];
    const float* W2   = (const float*)d_in[12];
    const float* b2   = (const float*)d_in[13];
    const float* ln2g = (const float*)d_in[14];
    const float* ln2b = (const float*)d_in[15];
    const float* lnfg = (const float*)d_in[16];
    const float* lnfb = (const float*)d_in[17];
    const float* Wlm  = (const float*)d_in[18];
    const float* blm  = (const float*)d_in[19];
    float* out = (float*)d_out;

    fp16 *wqkv,*wo,*w1,*w2,*wlm;
    fp16 *hA,*qA,*kA,*vtA,*oA,*ffA;
    float *x, *part;
    cudaGetSymbolAddress((void**)&wqkv, g_wqkv);
    cudaGetSymbolAddress((void**)&wo, g_wo);
    cudaGetSymbolAddress((void**)&w1, g_w1);
    cudaGetSymbolAddress((void**)&w2, g_w2);
    cudaGetSymbolAddress((void**)&wlm, g_wlm);
    cudaGetSymbolAddress((void**)&hA, g_h);
    cudaGetSymbolAddress((void**)&qA, g_q);
    cudaGetSymbolAddress((void**)&kA, g_k);
    cudaGetSymbolAddress((void**)&vtA, g_vt);
    cudaGetSymbolAddress((void**)&oA, g_o);
    cudaGetSymbolAddress((void**)&ffA, g_ff);
    cudaGetSymbolAddress((void**)&x, g_x);
    cudaGetSymbolAddress((void**)&part, g_part);

    cudaFuncSetAttribute(gemm_mma<0>, cudaFuncAttributeMaxDynamicSharedMemorySize, G_SMEM);
    cudaFuncSetAttribute(gemm_mma<1>, cudaFuncAttributeMaxDynamicSharedMemorySize, G_SMEM);
    cudaFuncSetAttribute(flash_kernel, cudaFuncAttributeMaxDynamicSharedMemorySize, FA_SMEM);

    const long long EE = (long long)E_ * E_;
    const long long NE = (long long)M_ * E_;
    const float scale = 1.0f / sqrtf((float)E_);
    int n4e = (int)(EE / 4);

    // launch 0: layer-0 QKV weight convert
    conv3_kernel<<<(3 * n4e + 255) / 256, 256>>>((const float4*)Wq, (const float4*)Wk,
        (const float4*)Wv, (__half2*)wqkv, n4e);
    // launch 1: embed
    embed_kernel<<<(int)(((long long)M_*E_ + 255)/256), 256>>>(idx, tok, pos, x);
    // launch 2: LN1 layer 0
    layernorm_kernel<<<M_, 256>>>(x, ln1g, ln1b, hA);
    // launch 3: layer-0 fused QKV GEMM (ncu target)
    {
        dim3 g(3 * E_ / 128, M_ / 128, 1);
        gemm_mma<0><<<g, 256, G_SMEM>>>(hA, E_, wqkv, E_,
            nullptr, qA, kA, vtA, E_, scale,
            E_, nullptr, nullptr, 0, E_, 0, 0);
    }

    // remaining weight converts
    for (int l = 1; l < L_; l++)
        conv3_kernel<<<(3 * n4e + 255) / 256, 256>>>(
            (const float4*)(Wq + l * EE), (const float4*)(Wk + l * EE), (const float4*)(Wv + l * EE),
            (__half2*)(wqkv + l * 3 * EE), n4e);
    conv_launch(Wo, wo, (long long)L_*E_*E_);
    conv_launch(W1, w1, (long long)L_*DF_*E_);
    conv_launch(W2, w2, (long long)L_*E_*DF_);
    conv_launch(Wlm, wlm, (long long)V_*E_);

    for (int l = 0; l < L_; l++) {
        if (l > 0) {
            dim3 g(3 * E_ / 128, M_ / 128, 1);
            gemm_mma<0><<<g, 256, G_SMEM>>>(hA, E_,
                wqkv + l * 3 * EE, E_,
                nullptr, qA, kA, vtA, E_, scale,
                E_, nullptr, nullptr, 0, E_, 0, 0);
        }

        {
            dim3 g(1, T_/128, B_*H_);
            flash_kernel<<<g, 256, FA_SMEM>>>(qA, kA, vtA, oA);
        }

        // Wo: split-K=3 (KS=256) -> partials, fused reduce+LN2 -> hA
        {
            dim3 g(E_/128, M_/128, 3);
            gemm_mma<0><<<g, 256, G_SMEM>>>(oA, E_, wo + l*EE, E_,
                part, nullptr, nullptr, nullptr, 0, 1.f,
                E_, nullptr, nullptr, 0, 256, 256, NE);
            reduce3_ln_kernel<<<M_, 256>>>(x, part, bo + l*E_, ln2g + l*E_, ln2b + l*E_, hA);
        }

        // ff = relu(h @ W1^T + b1)
        {
            dim3 g(DF_/128, M_/128, 1);
            gemm_mma<0><<<g, 256, G_SMEM>>>(hA, E_,
                w1 + (long long)l*DF_*E_, E_,
                nullptr, ffA, nullptr, nullptr, 0, 1.f,
                DF_, b1 + l*DF_, nullptr, 1, E_, 0, 0);
        }
        // FFN2: split-K=3 (KS=1024) -> partials, fused reduce + next LN -> hA
        {
            dim3 g(E_/128, M_/128, 3);
            gemm_mma<0><<<g, 256, G_SMEM>>>(ffA, DF_,
                w2 + (long long)l*E_*DF_, DF_,
                part, nullptr, nullptr, nullptr, 0, 1.f,
                E_, nullptr, nullptr, 0, 1024, 1024, NE);
            const float* ng = (l + 1 < L_) ? ln1g + (l+1)*E_ : lnfg;
            const float* nb = (l + 1 < L_) ? ln1b + (l+1)*E_ : lnfb;
            reduce3_ln_kernel<<<M_, 256>>>(x, part, b2 + l*E_, ng, nb, hA);
        }
    }

    // LM head: SWAP rasterization (x = M, y = N) so Wlm streams once
    {
        dim3 g(M_/128, V_/128, 1);
        gemm_mma<1><<<g, 256, G_SMEM>>>(hA, E_, wlm, E_,
            out, nullptr, nullptr, nullptr, 0, 1.f,
            V_, blm, nullptr, 0, E_, 0, 0);
    }
}